// round 16
// baseline (speedup 1.0000x reference)
#include <cuda_runtime.h>
#include <stdint.h>

constexpr int THREADS = 128;
constexpr int NBLK    = 444;        // 148 SMs x 3 resident CTAs: one persistent wave
constexpr float HSTEP  = 0.05f;     // 0.5 * dt_eff
constexpr float DT_EFF = 0.1f;
constexpr float CMU_H  = 0.00125f;  // 0.5 * h * FRICTION_SCALE
constexpr float TWO_PI     = 6.2831853071795864769f;
constexpr float INV_TWO_PI = 0.15915494309189533577f;

// ---------------- helpers ----------------
__device__ __forceinline__ uint32_t bf2(float lo, float hi){
    uint32_t r;
    asm("cvt.rn.bf16x2.f32 %0, %1, %2;" : "=r"(r) : "f"(hi), "f"(lo));
    return r;
}
__device__ __forceinline__ void split2(float x0, float x1, uint32_t& hi, uint32_t& lo){
    hi = bf2(x0, x1);
    float h0 = __uint_as_float(hi << 16);
    float h1 = __uint_as_float(hi & 0xFFFF0000u);
    lo = bf2(x0 - h0, x1 - h1);
}
__device__ __forceinline__ uint32_t pkh(float lo, float hi){
    uint32_t r; asm("cvt.rn.f16x2.f32 %0, %1, %2;" : "=r"(r) : "f"(hi), "f"(lo)); return r;
}
__device__ __forceinline__ float2 h2f2(uint32_t h){
    float2 r;
    asm("{ .reg .f16 lo, hi; mov.b32 {lo, hi}, %2; cvt.f32.f16 %0, lo; cvt.f32.f16 %1, hi; }"
        : "=f"(r.x), "=f"(r.y) : "r"(h));
    return r;
}
__device__ __forceinline__ float tanha(float x){
    float y; asm("tanh.approx.f32 %0, %1;" : "=f"(y) : "f"(x)); return y;
}
__device__ __forceinline__ float rdenf(float gate){
    float z = CMU_H * (1.0f + tanha(0.5f * gate));
    return fmaf(z, z, 1.0f) - z;
}
__device__ __forceinline__ void mma(float* c, uint32_t a0, uint32_t a1, uint32_t a2, uint32_t a3,
                                    uint32_t b0, uint32_t b1){
    asm("mma.sync.aligned.m16n8k16.row.col.f32.bf16.bf16.f32 "
        "{%0,%1,%2,%3}, {%4,%5,%6,%7}, {%8,%9}, {%0,%1,%2,%3};"
        : "+f"(c[0]), "+f"(c[1]), "+f"(c[2]), "+f"(c[3])
        : "r"(a0), "r"(a1), "r"(a2), "r"(a3), "r"(b0), "r"(b1));
}
// pair-scoped named barrier: warps {w, w^2} (64 threads) only
__device__ __forceinline__ void pairbar(int q){
    asm volatile("bar.sync %0, %1;" :: "r"(q + 1), "r"(64) : "memory");
}

// =====================================================================
// Persistent kernel (444 CTAs, tables built once). Per-tile body:
// pair-split K, pair-scoped barriers, f16-packed gate exchange, U/W frags
// in registers. R16: the standalone g1_reduce stage is dissolved — g1 of
// the fresh v is fused INTO g2half (interleaved with the n-tile loop) and
// into fused_gate at tile init, so every exchange overlaps independent
// MMA work and the per-step serial stage disappears.
// =====================================================================
__global__ void __launch_bounds__(THREADS, 3)
leapfrog_r16_kernel(const float* __restrict__ x_in, const float* __restrict__ v_in,
                    const float* __restrict__ f_in, const float* __restrict__ U_in,
                    const float* __restrict__ W_in, const float* __restrict__ Wf_in,
                    const float* __restrict__ bf_in, const int* __restrict__ steps_ptr,
                    float* __restrict__ out, int Btot)
{
    __shared__ uint4 sWf[8 * 32 * 5];   // gate B-frags [ktg][lane][4 uint4 + pad]
    __shared__ float sBias[64];
    __shared__ float sExA[128 * 12];    // a-partial exchange fp32 (8 used, stride 12)
    __shared__ float sExB[128 * 20];    // fused exchange: a fp32 [0..7] + gate f16x2 [8..15]

    const int tid = threadIdx.x, wid = tid >> 5, lane = tid & 31;
    const int g = lane >> 2, m = lane & 3;
    const int q  = wid & 1;        // row-block (names the pair barrier)
    const int hh = wid >> 1;       // column half
    const int cbase = 32 * hh + 2 * m;
    const int self    = (wid * 32 + lane);
    const int partner = ((wid ^ 2) * 32 + lane);

    // ---- gate B-frag table: Wf [64][128] -> B[n][k], all 8 k-tiles ----
    #pragma unroll
    for (int t = 0; t < 2; t++) {
        int kt = wid + 4 * t;
        #pragma unroll
        for (int j = 0; j < 4; j++) {
            const float* w0 = Wf_in + (8 * (2 * j)     + g) * 128 + 16 * kt;
            const float* w1 = Wf_in + (8 * (2 * j + 1) + g) * 128 + 16 * kt;
            uint4 qq;
            qq.x = bf2(w0[2 * m],     w0[2 * m + 1]);
            qq.y = bf2(w0[8 + 2 * m], w0[9 + 2 * m]);
            qq.z = bf2(w1[2 * m],     w1[2 * m + 1]);
            qq.w = bf2(w1[8 + 2 * m], w1[9 + 2 * m]);
            sWf[(kt * 32 + lane) * 5 + j] = qq;
        }
    }

    // ---- U frags (this warp's K-half): hi AND lo in registers ----
    uint32_t Uh[2][2][2];   // [ktl][nt][pair]
    uint4    Ulr[2];
    #pragma unroll
    for (int ktl = 0; ktl < 2; ktl++) {
        int ktg = 2 * hh + ktl;
        uint32_t lo[2][2];
        #pragma unroll
        for (int nt = 0; nt < 2; nt++) {
            const float* up = U_in + (8 * nt + g) * 64 + 16 * ktg;
            split2(up[2 * m],     up[2 * m + 1], Uh[ktl][nt][0], lo[nt][0]);
            split2(up[8 + 2 * m], up[9 + 2 * m], Uh[ktl][nt][1], lo[nt][1]);
        }
        Ulr[ktl] = make_uint4(lo[0][0], lo[0][1], lo[1][0], lo[1][1]);
    }

    // ---- W frags (this warp's N-half): hi AND lo in registers ----
    uint32_t Wh[4][2];
    uint4    Wlr[2];
    {
        uint32_t wlo[4][2];
        #pragma unroll
        for (int j = 0; j < 4; j++) {
            int n = 8 * (4 * hh + j) + g;
            split2(W_in[(2 * m) * 64 + n],     W_in[(2 * m + 1) * 64 + n], Wh[j][0], wlo[j][0]);
            split2(W_in[(2 * m + 8) * 64 + n], W_in[(2 * m + 9) * 64 + n], Wh[j][1], wlo[j][1]);
        }
        #pragma unroll
        for (int jj = 0; jj < 2; jj++)
            Wlr[jj] = make_uint4(wlo[2 * jj][0], wlo[2 * jj][1], wlo[2 * jj + 1][0], wlo[2 * jj + 1][1]);
    }
    if (tid < 64) sBias[tid] = bf_in[tid];

    __syncthreads();   // one CTA-wide barrier after tables; everything else pair-scoped

    const int steps = steps_ptr[0];
    const int ntiles = Btot / 32;

    float xr[16], vr[16], fr[16], rden[16];
    float aC[2][4];

    // ---- one g1 k-block (this warp's K-half tile ktl) ----
    auto g1_block = [&](int ktl, float aH[2][4], float aL[2][4]){
        uint32_t ah0, ah1, ah2, ah3, al0, al1, al2, al3;
        split2(vr[4 * ktl],      vr[4 * ktl + 1], ah0, al0);
        split2(vr[8 + 4 * ktl],  vr[9 + 4 * ktl], ah1, al1);
        split2(vr[4 * ktl + 2],  vr[4 * ktl + 3], ah2, al2);
        split2(vr[10 + 4 * ktl], vr[11 + 4 * ktl], ah3, al3);
        uint4 ql = Ulr[ktl];
        mma(aH[0], ah0, ah1, ah2, ah3, Uh[ktl][0][0], Uh[ktl][0][1]);
        mma(aH[1], ah0, ah1, ah2, ah3, Uh[ktl][1][0], Uh[ktl][1][1]);
        mma(aL[0], ah0, ah1, ah2, ah3, ql.x, ql.y);
        mma(aL[1], ah0, ah1, ah2, ah3, ql.z, ql.w);
        mma(aL[0], al0, al1, al2, al3, Uh[ktl][0][0], Uh[ktl][0][1]);
        mma(aL[1], al0, al1, al2, al3, Uh[ktl][1][0], Uh[ktl][1][1]);
    };

    // ---- fused: gate partial (+ optional g1), f16x2-packed gate exchange ----
    auto fused_gate = [&](bool with_g1){
        float gc[8][4];
        #pragma unroll
        for (int nt = 0; nt < 8; nt++)
            #pragma unroll
            for (int k = 0; k < 4; k++) gc[nt][k] = 0.0f;
        float aH[2][4], aL[2][4];
        if (with_g1) {
            #pragma unroll
            for (int nt = 0; nt < 2; nt++)
                #pragma unroll
                for (int k = 0; k < 4; k++) { aH[nt][k] = 0.f; aL[nt][k] = 0.f; }
        }
        #pragma unroll
        for (int ktl = 0; ktl < 2; ktl++) {
            float s0, c0, s1, c1;
            uint32_t a0, a1, a2, a3, c0p, c1p, c2p, c3p;
            __sincosf(xr[4 * ktl],      &s0, &c0);
            __sincosf(xr[4 * ktl + 1],  &s1, &c1);
            a0 = bf2(s0, s1); c0p = bf2(c0, c1);
            __sincosf(xr[8 + 4 * ktl],  &s0, &c0);
            __sincosf(xr[9 + 4 * ktl],  &s1, &c1);
            a1 = bf2(s0, s1); c1p = bf2(c0, c1);
            __sincosf(xr[4 * ktl + 2],  &s0, &c0);
            __sincosf(xr[4 * ktl + 3],  &s1, &c1);
            a2 = bf2(s0, s1); c2p = bf2(c0, c1);
            __sincosf(xr[10 + 4 * ktl], &s0, &c0);
            __sincosf(xr[11 + 4 * ktl], &s1, &c1);
            a3 = bf2(s0, s1); c3p = bf2(c0, c1);
            int ktgS = 2 * hh + ktl;       // sin k-tile
            int ktgC = 4 + 2 * hh + ktl;   // cos k-tile
            #pragma unroll
            for (int j = 0; j < 4; j++) {
                uint4 qs = sWf[(ktgS * 32 + lane) * 5 + j];
                mma(gc[2 * j],     a0, a1, a2, a3, qs.x, qs.y);
                mma(gc[2 * j + 1], a0, a1, a2, a3, qs.z, qs.w);
                uint4 qc = sWf[(ktgC * 32 + lane) * 5 + j];
                mma(gc[2 * j],     c0p, c1p, c2p, c3p, qc.x, qc.y);
                mma(gc[2 * j + 1], c0p, c1p, c2p, c3p, qc.z, qc.w);
            }
            if (with_g1) g1_block(ktl, aH, aL);
        }
        // exchange: a-partial fp32 [0..7] + other-half gate partial f16x2 [8..15]
        if (with_g1) {
            #pragma unroll
            for (int nt = 0; nt < 2; nt++) {
                float4 p = make_float4(aH[nt][0] + aL[nt][0], aH[nt][1] + aL[nt][1],
                                       aH[nt][2] + aL[nt][2], aH[nt][3] + aL[nt][3]);
                *(float4*)&sExB[self * 20 + 4 * nt] = p;
                aC[nt][0] = p.x; aC[nt][1] = p.y; aC[nt][2] = p.z; aC[nt][3] = p.w;
            }
        }
        const int oh = 1 - hh;
        {
            uint4 q0, q1;
            q0.x = pkh(gc[4 * oh + 0][0], gc[4 * oh + 0][1]);
            q0.y = pkh(gc[4 * oh + 0][2], gc[4 * oh + 0][3]);
            q0.z = pkh(gc[4 * oh + 1][0], gc[4 * oh + 1][1]);
            q0.w = pkh(gc[4 * oh + 1][2], gc[4 * oh + 1][3]);
            q1.x = pkh(gc[4 * oh + 2][0], gc[4 * oh + 2][1]);
            q1.y = pkh(gc[4 * oh + 2][2], gc[4 * oh + 2][3]);
            q1.z = pkh(gc[4 * oh + 3][0], gc[4 * oh + 3][1]);
            q1.w = pkh(gc[4 * oh + 3][2], gc[4 * oh + 3][3]);
            *(uint4*)&sExB[self * 20 + 8]  = q0;
            *(uint4*)&sExB[self * 20 + 12] = q1;
        }
        pairbar(q);
        if (with_g1) {
            #pragma unroll
            for (int nt = 0; nt < 2; nt++) {
                float4 p = *(const float4*)&sExB[partner * 20 + 4 * nt];
                aC[nt][0] += p.x; aC[nt][1] += p.y; aC[nt][2] += p.z; aC[nt][3] += p.w;
            }
        }
        {
            uint4 q0 = *(const uint4*)&sExB[partner * 20 + 8];
            uint4 q1 = *(const uint4*)&sExB[partner * 20 + 12];
            uint32_t pk[8] = {q0.x, q0.y, q0.z, q0.w, q1.x, q1.y, q1.z, q1.w};
            #pragma unroll
            for (int j = 0; j < 4; j++) {
                float2 pA = h2f2(pk[2 * j]);
                float2 pB = h2f2(pk[2 * j + 1]);
                float g0  = gc[4 * hh + j][0] + pA.x;
                float g1v = gc[4 * hh + j][1] + pA.y;
                float g2v = gc[4 * hh + j][2] + pB.x;
                float g3  = gc[4 * hh + j][3] + pB.y;
                float2 bb = *(const float2*)(sBias + 32 * hh + 8 * j + 2 * m);
                rden[2 * j]     = rdenf(g0 + bb.x);
                rden[2 * j + 1] = rdenf(g1v + bb.y);
                rden[8 + 2 * j] = rdenf(g2v + bb.x);
                rden[9 + 2 * j] = rdenf(g3 + bb.y);
            }
        }
    };

    // ---- g2 + state update, with NEXT g1 fused into the n-tile loop ----
    // After jj=0 the v-columns t={0,1} are final -> g1_block(0) can run;
    // after jj=1, g1_block(1). Exchange via sExA overlaps nothing serial.
    auto g2half = [&](bool first){
        uint32_t h0, h1, h2, h3, l0, l1, l2, l3;
        split2(aC[0][0] * aC[0][0], aC[0][1] * aC[0][1], h0, l0);
        split2(aC[0][2] * aC[0][2], aC[0][3] * aC[0][3], h1, l1);
        split2(aC[1][0] * aC[1][0], aC[1][1] * aC[1][1], h2, l2);
        split2(aC[1][2] * aC[1][2], aC[1][3] * aC[1][3], h3, l3);
        float aH[2][4], aL[2][4];
        if (!first) {
            #pragma unroll
            for (int nt = 0; nt < 2; nt++)
                #pragma unroll
                for (int k = 0; k < 4; k++) { aH[nt][k] = 0.f; aL[nt][k] = 0.f; }
        }
        #pragma unroll
        for (int jj = 0; jj < 2; jj++) {
            uint4 ql = Wlr[jj];
            uint32_t Wlf[2][2] = {{ql.x, ql.y}, {ql.z, ql.w}};
            #pragma unroll
            for (int u = 0; u < 2; u++) {
                int j = 2 * jj + u;
                float gA[4] = {0.f, 0.f, 0.f, 0.f};
                float gB[4] = {0.f, 0.f, 0.f, 0.f};
                mma(gA, h0, h1, h2, h3, Wh[j][0], Wh[j][1]);
                mma(gB, h0, h1, h2, h3, Wlf[u][0], Wlf[u][1]);
                mma(gA, l0, l1, l2, l3, Wh[j][0], Wh[j][1]);
                #pragma unroll
                for (int k = 0; k < 4; k++) {
                    int i = (k >> 1) * 8 + 2 * j + (k & 1);
                    float gm = gA[k] + gB[k];
                    float vn = (vr[i] + HSTEP * (fr[i] - gm)) * rden[i];
                    vr[i] = vn;
                    if (first) xr[i] = fmaf(DT_EFF, vn, xr[i]);
                }
            }
            if (!first) g1_block(jj, aH, aL);   // v cols t={2jj,2jj+1} are final
        }
        if (!first) {
            // a(v_final) partial exchange via sExA (consumed by next step's g2half(true))
            #pragma unroll
            for (int nt = 0; nt < 2; nt++) {
                float4 p = make_float4(aH[nt][0] + aL[nt][0], aH[nt][1] + aL[nt][1],
                                       aH[nt][2] + aL[nt][2], aH[nt][3] + aL[nt][3]);
                *(float4*)&sExA[self * 12 + 4 * nt] = p;
                aC[nt][0] = p.x; aC[nt][1] = p.y; aC[nt][2] = p.z; aC[nt][3] = p.w;
            }
            pairbar(q);
            #pragma unroll
            for (int nt = 0; nt < 2; nt++) {
                float4 p = *(const float4*)&sExA[partner * 12 + 4 * nt];
                aC[nt][0] += p.x; aC[nt][1] += p.y; aC[nt][2] += p.z; aC[nt][3] += p.w;
            }
        }
    };

    // ==================== persistent tile loop ====================
    for (int tile = blockIdx.x; tile < ntiles; tile += NBLK) {
        const int r0 = tile * 32 + q * 16 + g;

        // ---- state into registers ----
        #pragma unroll
        for (int rr = 0; rr < 2; rr++) {
            const size_t base = (size_t)(r0 + 8 * rr) * 64 + cbase;
            #pragma unroll
            for (int t = 0; t < 4; t++) {
                float2 tt;
                tt = *(const float2*)(x_in + base + 8 * t); xr[rr * 8 + 2 * t] = tt.x; xr[rr * 8 + 2 * t + 1] = tt.y;
                tt = *(const float2*)(v_in + base + 8 * t); vr[rr * 8 + 2 * t] = tt.x; vr[rr * 8 + 2 * t + 1] = tt.y;
                tt = *(const float2*)(f_in + base + 8 * t); fr[rr * 8 + 2 * t] = tt.x; fr[rr * 8 + 2 * t + 1] = tt.y;
            }
        }

        // ---- tile init: mu(x0) and a(v0), fused ----
        fused_gate(true);

        // ---- main loop (pair barriers only, no standalone g1 stage) ----
        for (int s = 0; s < steps; s++) {
            g2half(true);              // v_half, x update (uses aC, rden)
            fused_gate(true);          // mu(x_new) + a(v_half), reduced
            g2half(false);             // final v + a(v_final) fused + exchange
        }

        // ---- output: wrap x, write x then v ----
        #pragma unroll
        for (int rr = 0; rr < 2; rr++) {
            const size_t base = (size_t)(r0 + 8 * rr) * 64 + cbase;
            #pragma unroll
            for (int t = 0; t < 4; t++) {
                float X0 = xr[rr * 8 + 2 * t], X1 = xr[rr * 8 + 2 * t + 1];
                float2 qx;
                qx.x = fmaf(-TWO_PI, rintf(X0 * INV_TWO_PI), X0);
                qx.y = fmaf(-TWO_PI, rintf(X1 * INV_TWO_PI), X1);
                *(float2*)(out + base + 8 * t) = qx;
                float2 qv = make_float2(vr[rr * 8 + 2 * t], vr[rr * 8 + 2 * t + 1]);
                *(float2*)(out + (size_t)Btot * 64 + base + 8 * t) = qv;
            }
        }
    }
}

extern "C" void kernel_launch(void* const* d_in, const int* in_sizes, int n_in,
                              void* d_out, int out_size)
{
    const float* x  = (const float*)d_in[0];
    const float* v  = (const float*)d_in[1];
    const float* f  = (const float*)d_in[2];
    const float* U  = (const float*)d_in[3];
    const float* W  = (const float*)d_in[4];
    const float* Wf = (const float*)d_in[5];
    const float* bf = (const float*)d_in[6];
    const int* steps = (const int*)d_in[7];

    float* out = (float*)d_out;
    const int Btot = in_sizes[0] / 64;     // 262144
    const int ntiles = Btot / 32;          // 8192
    const int blocks = (ntiles < NBLK) ? ntiles : NBLK;   // persistent: one wave

    leapfrog_r16_kernel<<<blocks, THREADS>>>(x, v, f, U, W, Wf, bf, steps, out, Btot);
}

// round 17
// speedup vs baseline: 1.0063x; 1.0063x over previous
#include <cuda_runtime.h>
#include <stdint.h>

constexpr int THREADS = 128;
constexpr int NBLK    = 444;        // 148 SMs x 3 resident CTAs: one persistent wave
constexpr float HSTEP  = 0.05f;     // 0.5 * dt_eff
constexpr float DT_EFF = 0.1f;
constexpr float CMU_H  = 0.00125f;  // 0.5 * h * FRICTION_SCALE
constexpr float TWO_PI     = 6.2831853071795864769f;
constexpr float INV_TWO_PI = 0.15915494309189533577f;

// ---------------- helpers ----------------
__device__ __forceinline__ uint32_t bf2(float lo, float hi){
    uint32_t r;
    asm("cvt.rn.bf16x2.f32 %0, %1, %2;" : "=r"(r) : "f"(hi), "f"(lo));
    return r;
}
__device__ __forceinline__ void split2(float x0, float x1, uint32_t& hi, uint32_t& lo){
    hi = bf2(x0, x1);
    float h0 = __uint_as_float(hi << 16);
    float h1 = __uint_as_float(hi & 0xFFFF0000u);
    lo = bf2(x0 - h0, x1 - h1);
}
__device__ __forceinline__ uint32_t pkh(float lo, float hi){
    uint32_t r; asm("cvt.rn.f16x2.f32 %0, %1, %2;" : "=r"(r) : "f"(hi), "f"(lo)); return r;
}
__device__ __forceinline__ float2 h2f2(uint32_t h){
    float2 r;
    asm("{ .reg .f16 lo, hi; mov.b32 {lo, hi}, %2; cvt.f32.f16 %0, lo; cvt.f32.f16 %1, hi; }"
        : "=f"(r.x), "=f"(r.y) : "r"(h));
    return r;
}
__device__ __forceinline__ float tanha(float x){
    float y; asm("tanh.approx.f32 %0, %1;" : "=f"(y) : "f"(x)); return y;
}
__device__ __forceinline__ float rdenf(float gate){
    float z = CMU_H * (1.0f + tanha(0.5f * gate));
    return fmaf(z, z, 1.0f) - z;
}
__device__ __forceinline__ void mma(float* c, uint32_t a0, uint32_t a1, uint32_t a2, uint32_t a3,
                                    uint32_t b0, uint32_t b1){
    asm("mma.sync.aligned.m16n8k16.row.col.f32.bf16.bf16.f32 "
        "{%0,%1,%2,%3}, {%4,%5,%6,%7}, {%8,%9}, {%0,%1,%2,%3};"
        : "+f"(c[0]), "+f"(c[1]), "+f"(c[2]), "+f"(c[3])
        : "r"(a0), "r"(a1), "r"(a2), "r"(a3), "r"(b0), "r"(b1));
}
// pair-scoped named barrier: warps {w, w^2} (64 threads) only
__device__ __forceinline__ void pairbar(int q){
    asm volatile("bar.sync %0, %1;" :: "r"(q + 1), "r"(64) : "memory");
}
__device__ __forceinline__ void pref_l2(const float* p){
    asm volatile("prefetch.global.L2 [%0];" :: "l"(p));
}

// =====================================================================
// Persistent kernel: 444 CTAs build the weight-fragment tables ONCE and
// loop over tiles (32 rows each) with stride 444. Per-tile body identical
// to R15 (best): pair-split K, pair-scoped barriers, f16-packed gate
// exchange, U/W frags in registers. R17 adds L2 prefetch of the NEXT
// tile's state at the top of each tile.
// =====================================================================
__global__ void __launch_bounds__(THREADS, 3)
leapfrog_r17_kernel(const float* __restrict__ x_in, const float* __restrict__ v_in,
                    const float* __restrict__ f_in, const float* __restrict__ U_in,
                    const float* __restrict__ W_in, const float* __restrict__ Wf_in,
                    const float* __restrict__ bf_in, const int* __restrict__ steps_ptr,
                    float* __restrict__ out, int Btot)
{
    __shared__ uint4 sWf[8 * 32 * 5];   // gate B-frags [ktg][lane][4 uint4 + pad]
    __shared__ float sBias[64];
    __shared__ float sExA[128 * 12];    // a-partial exchange fp32 (8 used, stride 12)
    __shared__ float sExB[128 * 20];    // fused exchange: a fp32 [0..7] + gate f16x2 [8..15]

    const int tid = threadIdx.x, wid = tid >> 5, lane = tid & 31;
    const int g = lane >> 2, m = lane & 3;
    const int q  = wid & 1;        // row-block (names the pair barrier)
    const int hh = wid >> 1;       // column half
    const int cbase = 32 * hh + 2 * m;
    const int self    = (wid * 32 + lane);
    const int partner = ((wid ^ 2) * 32 + lane);

    // ---- gate B-frag table: Wf [64][128] -> B[n][k], all 8 k-tiles ----
    #pragma unroll
    for (int t = 0; t < 2; t++) {
        int kt = wid + 4 * t;
        #pragma unroll
        for (int j = 0; j < 4; j++) {
            const float* w0 = Wf_in + (8 * (2 * j)     + g) * 128 + 16 * kt;
            const float* w1 = Wf_in + (8 * (2 * j + 1) + g) * 128 + 16 * kt;
            uint4 qq;
            qq.x = bf2(w0[2 * m],     w0[2 * m + 1]);
            qq.y = bf2(w0[8 + 2 * m], w0[9 + 2 * m]);
            qq.z = bf2(w1[2 * m],     w1[2 * m + 1]);
            qq.w = bf2(w1[8 + 2 * m], w1[9 + 2 * m]);
            sWf[(kt * 32 + lane) * 5 + j] = qq;
        }
    }

    // ---- U frags (this warp's K-half): hi AND lo in registers ----
    uint32_t Uh[2][2][2];   // [ktl][nt][pair]
    uint4    Ulr[2];
    #pragma unroll
    for (int ktl = 0; ktl < 2; ktl++) {
        int ktg = 2 * hh + ktl;
        uint32_t lo[2][2];
        #pragma unroll
        for (int nt = 0; nt < 2; nt++) {
            const float* up = U_in + (8 * nt + g) * 64 + 16 * ktg;
            split2(up[2 * m],     up[2 * m + 1], Uh[ktl][nt][0], lo[nt][0]);
            split2(up[8 + 2 * m], up[9 + 2 * m], Uh[ktl][nt][1], lo[nt][1]);
        }
        Ulr[ktl] = make_uint4(lo[0][0], lo[0][1], lo[1][0], lo[1][1]);
    }

    // ---- W frags (this warp's N-half): hi AND lo in registers ----
    uint32_t Wh[4][2];
    uint4    Wlr[2];
    {
        uint32_t wlo[4][2];
        #pragma unroll
        for (int j = 0; j < 4; j++) {
            int n = 8 * (4 * hh + j) + g;
            split2(W_in[(2 * m) * 64 + n],     W_in[(2 * m + 1) * 64 + n], Wh[j][0], wlo[j][0]);
            split2(W_in[(2 * m + 8) * 64 + n], W_in[(2 * m + 9) * 64 + n], Wh[j][1], wlo[j][1]);
        }
        #pragma unroll
        for (int jj = 0; jj < 2; jj++)
            Wlr[jj] = make_uint4(wlo[2 * jj][0], wlo[2 * jj][1], wlo[2 * jj + 1][0], wlo[2 * jj + 1][1]);
    }
    if (tid < 64) sBias[tid] = bf_in[tid];

    __syncthreads();   // one CTA-wide barrier after tables; everything else pair-scoped

    const int steps = steps_ptr[0];
    const int ntiles = Btot / 32;

    float xr[16], vr[16], fr[16], rden[16];
    float aC[2][4];

    // ---- one g1 k-block (this warp's K-half tile ktl) ----
    auto g1_block = [&](int ktl, float aH[2][4], float aL[2][4]){
        uint32_t ah0, ah1, ah2, ah3, al0, al1, al2, al3;
        split2(vr[4 * ktl],      vr[4 * ktl + 1], ah0, al0);
        split2(vr[8 + 4 * ktl],  vr[9 + 4 * ktl], ah1, al1);
        split2(vr[4 * ktl + 2],  vr[4 * ktl + 3], ah2, al2);
        split2(vr[10 + 4 * ktl], vr[11 + 4 * ktl], ah3, al3);
        uint4 ql = Ulr[ktl];
        mma(aH[0], ah0, ah1, ah2, ah3, Uh[ktl][0][0], Uh[ktl][0][1]);
        mma(aH[1], ah0, ah1, ah2, ah3, Uh[ktl][1][0], Uh[ktl][1][1]);
        mma(aL[0], ah0, ah1, ah2, ah3, ql.x, ql.y);
        mma(aL[1], ah0, ah1, ah2, ah3, ql.z, ql.w);
        mma(aL[0], al0, al1, al2, al3, Uh[ktl][0][0], Uh[ktl][0][1]);
        mma(aL[1], al0, al1, al2, al3, Uh[ktl][1][0], Uh[ktl][1][1]);
    };

    // ---- standalone g1 partial + pair exchange through sExA ----
    auto g1_reduce = [&](){
        float aH[2][4], aL[2][4];
        #pragma unroll
        for (int nt = 0; nt < 2; nt++)
            #pragma unroll
            for (int k = 0; k < 4; k++) { aH[nt][k] = 0.f; aL[nt][k] = 0.f; }
        g1_block(0, aH, aL);
        g1_block(1, aH, aL);
        #pragma unroll
        for (int nt = 0; nt < 2; nt++) {
            float4 p = make_float4(aH[nt][0] + aL[nt][0], aH[nt][1] + aL[nt][1],
                                   aH[nt][2] + aL[nt][2], aH[nt][3] + aL[nt][3]);
            *(float4*)&sExA[self * 12 + 4 * nt] = p;
            aC[nt][0] = p.x; aC[nt][1] = p.y; aC[nt][2] = p.z; aC[nt][3] = p.w;
        }
        pairbar(q);
        #pragma unroll
        for (int nt = 0; nt < 2; nt++) {
            float4 p = *(const float4*)&sExA[partner * 12 + 4 * nt];
            aC[nt][0] += p.x; aC[nt][1] += p.y; aC[nt][2] += p.z; aC[nt][3] += p.w;
        }
    };

    // ---- fused: gate partial (+ optional g1), f16x2-packed gate exchange ----
    auto fused_gate = [&](bool with_g1){
        float gc[8][4];
        #pragma unroll
        for (int nt = 0; nt < 8; nt++)
            #pragma unroll
            for (int k = 0; k < 4; k++) gc[nt][k] = 0.0f;
        float aH[2][4], aL[2][4];
        if (with_g1) {
            #pragma unroll
            for (int nt = 0; nt < 2; nt++)
                #pragma unroll
                for (int k = 0; k < 4; k++) { aH[nt][k] = 0.f; aL[nt][k] = 0.f; }
        }
        #pragma unroll
        for (int ktl = 0; ktl < 2; ktl++) {
            float s0, c0, s1, c1;
            uint32_t a0, a1, a2, a3, c0p, c1p, c2p, c3p;
            __sincosf(xr[4 * ktl],      &s0, &c0);
            __sincosf(xr[4 * ktl + 1],  &s1, &c1);
            a0 = bf2(s0, s1); c0p = bf2(c0, c1);
            __sincosf(xr[8 + 4 * ktl],  &s0, &c0);
            __sincosf(xr[9 + 4 * ktl],  &s1, &c1);
            a1 = bf2(s0, s1); c1p = bf2(c0, c1);
            __sincosf(xr[4 * ktl + 2],  &s0, &c0);
            __sincosf(xr[4 * ktl + 3],  &s1, &c1);
            a2 = bf2(s0, s1); c2p = bf2(c0, c1);
            __sincosf(xr[10 + 4 * ktl], &s0, &c0);
            __sincosf(xr[11 + 4 * ktl], &s1, &c1);
            a3 = bf2(s0, s1); c3p = bf2(c0, c1);
            int ktgS = 2 * hh + ktl;       // sin k-tile
            int ktgC = 4 + 2 * hh + ktl;   // cos k-tile
            #pragma unroll
            for (int j = 0; j < 4; j++) {
                uint4 qs = sWf[(ktgS * 32 + lane) * 5 + j];
                mma(gc[2 * j],     a0, a1, a2, a3, qs.x, qs.y);
                mma(gc[2 * j + 1], a0, a1, a2, a3, qs.z, qs.w);
                uint4 qc = sWf[(ktgC * 32 + lane) * 5 + j];
                mma(gc[2 * j],     c0p, c1p, c2p, c3p, qc.x, qc.y);
                mma(gc[2 * j + 1], c0p, c1p, c2p, c3p, qc.z, qc.w);
            }
            if (with_g1) g1_block(ktl, aH, aL);
        }
        // exchange: a-partial fp32 [0..7] + other-half gate partial f16x2 [8..15]
        if (with_g1) {
            #pragma unroll
            for (int nt = 0; nt < 2; nt++) {
                float4 p = make_float4(aH[nt][0] + aL[nt][0], aH[nt][1] + aL[nt][1],
                                       aH[nt][2] + aL[nt][2], aH[nt][3] + aL[nt][3]);
                *(float4*)&sExB[self * 20 + 4 * nt] = p;
                aC[nt][0] = p.x; aC[nt][1] = p.y; aC[nt][2] = p.z; aC[nt][3] = p.w;
            }
        }
        const int oh = 1 - hh;
        {
            uint4 q0, q1;
            q0.x = pkh(gc[4 * oh + 0][0], gc[4 * oh + 0][1]);
            q0.y = pkh(gc[4 * oh + 0][2], gc[4 * oh + 0][3]);
            q0.z = pkh(gc[4 * oh + 1][0], gc[4 * oh + 1][1]);
            q0.w = pkh(gc[4 * oh + 1][2], gc[4 * oh + 1][3]);
            q1.x = pkh(gc[4 * oh + 2][0], gc[4 * oh + 2][1]);
            q1.y = pkh(gc[4 * oh + 2][2], gc[4 * oh + 2][3]);
            q1.z = pkh(gc[4 * oh + 3][0], gc[4 * oh + 3][1]);
            q1.w = pkh(gc[4 * oh + 3][2], gc[4 * oh + 3][3]);
            *(uint4*)&sExB[self * 20 + 8]  = q0;
            *(uint4*)&sExB[self * 20 + 12] = q1;
        }
        pairbar(q);
        if (with_g1) {
            #pragma unroll
            for (int nt = 0; nt < 2; nt++) {
                float4 p = *(const float4*)&sExB[partner * 20 + 4 * nt];
                aC[nt][0] += p.x; aC[nt][1] += p.y; aC[nt][2] += p.z; aC[nt][3] += p.w;
            }
        }
        {
            uint4 q0 = *(const uint4*)&sExB[partner * 20 + 8];
            uint4 q1 = *(const uint4*)&sExB[partner * 20 + 12];
            uint32_t pk[8] = {q0.x, q0.y, q0.z, q0.w, q1.x, q1.y, q1.z, q1.w};
            #pragma unroll
            for (int j = 0; j < 4; j++) {
                float2 pA = h2f2(pk[2 * j]);
                float2 pB = h2f2(pk[2 * j + 1]);
                float g0  = gc[4 * hh + j][0] + pA.x;
                float g1v = gc[4 * hh + j][1] + pA.y;
                float g2v = gc[4 * hh + j][2] + pB.x;
                float g3  = gc[4 * hh + j][3] + pB.y;
                float2 bb = *(const float2*)(sBias + 32 * hh + 8 * j + 2 * m);
                rden[2 * j]     = rdenf(g0 + bb.x);
                rden[2 * j + 1] = rdenf(g1v + bb.y);
                rden[8 + 2 * j] = rdenf(g2v + bb.x);
                rden[9 + 2 * j] = rdenf(g3 + bb.y);
            }
        }
    };

    // ---- g2 fused with state update, 2-way parallel accumulators ----
    auto g2half = [&](bool first){
        uint32_t h0, h1, h2, h3, l0, l1, l2, l3;
        split2(aC[0][0] * aC[0][0], aC[0][1] * aC[0][1], h0, l0);
        split2(aC[0][2] * aC[0][2], aC[0][3] * aC[0][3], h1, l1);
        split2(aC[1][0] * aC[1][0], aC[1][1] * aC[1][1], h2, l2);
        split2(aC[1][2] * aC[1][2], aC[1][3] * aC[1][3], h3, l3);
        #pragma unroll
        for (int jj = 0; jj < 2; jj++) {
            uint4 ql = Wlr[jj];
            uint32_t Wlf[2][2] = {{ql.x, ql.y}, {ql.z, ql.w}};
            #pragma unroll
            for (int u = 0; u < 2; u++) {
                int j = 2 * jj + u;
                float gA[4] = {0.f, 0.f, 0.f, 0.f};
                float gB[4] = {0.f, 0.f, 0.f, 0.f};
                mma(gA, h0, h1, h2, h3, Wh[j][0], Wh[j][1]);
                mma(gB, h0, h1, h2, h3, Wlf[u][0], Wlf[u][1]);
                mma(gA, l0, l1, l2, l3, Wh[j][0], Wh[j][1]);
                #pragma unroll
                for (int k = 0; k < 4; k++) {
                    int i = (k >> 1) * 8 + 2 * j + (k & 1);
                    float gm = gA[k] + gB[k];
                    float vn = (vr[i] + HSTEP * (fr[i] - gm)) * rden[i];
                    vr[i] = vn;
                    if (first) xr[i] = fmaf(DT_EFF, vn, xr[i]);
                }
            }
        }
    };

    // ==================== persistent tile loop ====================
    for (int tile = blockIdx.x; tile < ntiles; tile += NBLK) {
        const int r0 = tile * 32 + q * 16 + g;

        // ---- state into registers ----
        #pragma unroll
        for (int rr = 0; rr < 2; rr++) {
            const size_t base = (size_t)(r0 + 8 * rr) * 64 + cbase;
            #pragma unroll
            for (int t = 0; t < 4; t++) {
                float2 tt;
                tt = *(const float2*)(x_in + base + 8 * t); xr[rr * 8 + 2 * t] = tt.x; xr[rr * 8 + 2 * t + 1] = tt.y;
                tt = *(const float2*)(v_in + base + 8 * t); vr[rr * 8 + 2 * t] = tt.x; vr[rr * 8 + 2 * t + 1] = tt.y;
                tt = *(const float2*)(f_in + base + 8 * t); fr[rr * 8 + 2 * t] = tt.x; fr[rr * 8 + 2 * t + 1] = tt.y;
            }
        }

        // ---- L2-prefetch next tile's state (lanes collectively cover all lines) ----
        if (tile + NBLK < ntiles) {
            const size_t pb0 = (size_t)r0 * 64 + cbase + (size_t)NBLK * 32 * 64;
            const size_t pb1 = pb0 + 8 * 64;
            pref_l2(x_in + pb0); pref_l2(x_in + pb1);
            pref_l2(v_in + pb0); pref_l2(v_in + pb1);
            pref_l2(f_in + pb0); pref_l2(f_in + pb1);
        }

        // ---- initial friction at x0 ----
        fused_gate(false);

        // ---- main loop (pair barriers only) ----
        for (int s = 0; s < steps; s++) {
            g1_reduce();               // a(v), reduced across K-halves
            g2half(true);              // v_half, x update (rden = mu at old x)
            fused_gate(true);          // mu(x_new) + a(v_half), reduced
            g2half(false);             // final v
        }

        // ---- output: wrap x, write x then v ----
        #pragma unroll
        for (int rr = 0; rr < 2; rr++) {
            const size_t base = (size_t)(r0 + 8 * rr) * 64 + cbase;
            #pragma unroll
            for (int t = 0; t < 4; t++) {
                float X0 = xr[rr * 8 + 2 * t], X1 = xr[rr * 8 + 2 * t + 1];
                float2 qx;
                qx.x = fmaf(-TWO_PI, rintf(X0 * INV_TWO_PI), X0);
                qx.y = fmaf(-TWO_PI, rintf(X1 * INV_TWO_PI), X1);
                *(float2*)(out + base + 8 * t) = qx;
                float2 qv = make_float2(vr[rr * 8 + 2 * t], vr[rr * 8 + 2 * t + 1]);
                *(float2*)(out + (size_t)Btot * 64 + base + 8 * t) = qv;
            }
        }
    }
}

extern "C" void kernel_launch(void* const* d_in, const int* in_sizes, int n_in,
                              void* d_out, int out_size)
{
    const float* x  = (const float*)d_in[0];
    const float* v  = (const float*)d_in[1];
    const float* f  = (const float*)d_in[2];
    const float* U  = (const float*)d_in[3];
    const float* W  = (const float*)d_in[4];
    const float* Wf = (const float*)d_in[5];
    const float* bf = (const float*)d_in[6];
    const int* steps = (const int*)d_in[7];

    float* out = (float*)d_out;
    const int Btot = in_sizes[0] / 64;     // 262144
    const int ntiles = Btot / 32;          // 8192
    const int blocks = (ntiles < NBLK) ? ntiles : NBLK;   // persistent: one wave

    leapfrog_r17_kernel<<<blocks, THREADS>>>(x, v, f, U, W, Wf, bf, steps, out, Btot);
}